// round 5
// baseline (speedup 1.0000x reference)
#include <cuda_runtime.h>
#include <cuda_bf16.h>
#include <math.h>

// Problem constants (fixed by the reference setup)
#define NN 38332            // nodes = POI_LEN - 1
#define FF 544              // graph features
#define CC 128              // channels
#define EE (NN * 16)        // edges = 613312
#define PP 38333            // POI_LEN (output size)
#define LL 4                // gcn layers

// ---------------- device scratch (static globals; no allocation) ------------
__device__ float g_EF[(size_t)NN * FF];   // emb_feature materialized  (~83 MB)
__device__ float g_H [(size_t)NN * CC];   // GEMM output / message src (~20 MB)
__device__ float g_X [(size_t)NN * CC];   // node state between layers (~20 MB)
__device__ int   g_degi[NN];              // degree (incl. self loop)
__device__ float g_dinv[NN];              // deg^-1/2
__device__ int   g_poi[NN];               // poi ids
__device__ int   g_idxcol[NN];            // argmax(mask) column per row
__device__ int   g_rowStart[NN + 1];      // CSR row offsets (by dst)
__device__ int   g_cur[NN];               // bucket fill cursors
__device__ int   g_srcSorted[EE];         // CSR column (src) indices
__device__ float g_wSorted[EE];           // per-edge norm = dinv[s]*dinv[d]
__device__ float g_h1[NN];                // X @ W_out
__device__ float g_xvec[NN];              // post output-conv activations
__device__ float g_fc1acc[CC];            // fc1 partial accumulator

// ---------------- small helpers ---------------------------------------------
__device__ __forceinline__ float lrelu(float t) { return t >= 0.f ? t : 0.01f * t; }

// ---------------- setup kernels ----------------------------------------------

// idxcol[i] = first true column of mask row i (0 if none); poi[i] = (int)feature[i, idxcol]
__global__ void k_poi(const unsigned char* __restrict__ mask,
                      const float* __restrict__ feature) {
    int i = blockIdx.x * blockDim.x + threadIdx.x;
    if (i >= NN) return;
    const unsigned char* row = mask + (size_t)i * FF;
    int idx = 0;
    for (int j = 0; j < FF; j++) { if (row[j]) { idx = j; break; } }
    g_idxcol[i] = idx;
    g_poi[i] = (int)feature[(size_t)i * FF + idx];
}

// bulk copy feature -> g_EF (float4)
__global__ void k_build_ef(const float* __restrict__ feature) {
    size_t idx = (size_t)blockIdx.x * blockDim.x + threadIdx.x;
    size_t total4 = (size_t)NN * FF / 4;
    if (idx >= total4) return;
    reinterpret_cast<float4*>(g_EF)[idx] =
        reinterpret_cast<const float4*>(feature)[idx];
}

// masked_scatter semantics: EF[i, idxcol[i]] = emb[poi[i/128], i%128]
__global__ void k_fix_ef(const float* __restrict__ emb) {
    int i = blockIdx.x * blockDim.x + threadIdx.x;
    if (i >= NN) return;
    int p = g_poi[i >> 7];
    g_EF[(size_t)i * FF + g_idxcol[i]] = emb[(size_t)p * CC + (i & 127)];
}

__global__ void k_deg_init() {
    int i = blockIdx.x * blockDim.x + threadIdx.x;
    if (i < NN) g_degi[i] = 1;   // self loop
}

__global__ void k_deg_count(const int* __restrict__ dst) {
    int e = blockIdx.x * blockDim.x + threadIdx.x;
    if (e < EE) atomicAdd(&g_degi[dst[e]], 1);
}

// single-block exclusive scan of (deg-1); also fills g_cur and g_dinv
__global__ void k_scan() {
    __shared__ int s[1024];
    __shared__ int carrySh;
    int tid = threadIdx.x;
    if (tid == 0) carrySh = 0;
    __syncthreads();
    for (int base = 0; base < NN; base += 1024) {
        int idx = base + tid;
        int v = (idx < NN) ? (g_degi[idx] - 1) : 0;
        s[tid] = v;
        __syncthreads();
        for (int off = 1; off < 1024; off <<= 1) {
            int t = (tid >= off) ? s[tid - off] : 0;
            __syncthreads();
            s[tid] += t;
            __syncthreads();
        }
        int carry = carrySh;
        if (idx < NN) {
            int excl = carry + s[tid] - v;
            g_rowStart[idx] = excl;
            g_cur[idx]      = excl;
            g_dinv[idx]     = rsqrtf((float)g_degi[idx]);
        }
        __syncthreads();
        if (tid == 1023) carrySh = carry + s[1023];
        __syncthreads();
    }
    if (tid == 0) g_rowStart[NN] = carrySh;   // == EE
}

__global__ void k_bucket(const int* __restrict__ src, const int* __restrict__ dst) {
    int e = blockIdx.x * blockDim.x + threadIdx.x;
    if (e >= EE) return;
    int s = src[e], d = dst[e];
    int pos = atomicAdd(&g_cur[d], 1);
    g_srcSorted[pos] = s;
    g_wSorted[pos]   = g_dinv[s] * g_dinv[d];
}

__global__ void k_zero128() { g_fc1acc[threadIdx.x] = 0.f; }

// ---------------- SGEMM: C[M,128] = A[M,K] @ B[K,128] ------------------------
// BM=128, BN=128, BK=16, 256 threads, 8x8 register tile per thread.
template <int K, bool FROM_EF>
__global__ void __launch_bounds__(256) k_sgemm(const float* __restrict__ B) {
    const float* A = FROM_EF ? g_EF : g_X;
    float*       C = g_H;
    const int M = NN;
    const int BK = 16, TM = 8, TN = 8;

    __shared__ float As[BK][128];
    __shared__ float Bs[BK][128];

    int blockRow = blockIdx.x * 128;
    int tid = threadIdx.x;
    int tr = tid / 16;      // 0..15
    int tc = tid % 16;      // 0..15

    float acc[TM][TN] = {};
    float ra[TM], rb[TN];

    int aRow0 = tid / 4;    // 0..63  (loads rows aRow0, aRow0+64)
    int aCol4 = tid % 4;    // float4 column within BK=16
    int bRow0 = tid / 32;   // 0..7   (loads rows bRow0, bRow0+8)
    int bCol4 = tid % 32;

    for (int k0 = 0; k0 < K; k0 += BK) {
        #pragma unroll
        for (int i = 0; i < 2; i++) {
            int r = aRow0 + i * 64;
            int gr = blockRow + r;
            float4 v = make_float4(0.f, 0.f, 0.f, 0.f);
            if (gr < M)
                v = *reinterpret_cast<const float4*>(A + (size_t)gr * K + k0 + aCol4 * 4);
            As[aCol4 * 4 + 0][r] = v.x;
            As[aCol4 * 4 + 1][r] = v.y;
            As[aCol4 * 4 + 2][r] = v.z;
            As[aCol4 * 4 + 3][r] = v.w;
        }
        #pragma unroll
        for (int i = 0; i < 2; i++) {
            int r = bRow0 + i * 8;
            *reinterpret_cast<float4*>(&Bs[r][bCol4 * 4]) =
                *reinterpret_cast<const float4*>(B + (size_t)(k0 + r) * 128 + bCol4 * 4);
        }
        __syncthreads();
        #pragma unroll
        for (int k = 0; k < BK; k++) {
            #pragma unroll
            for (int i = 0; i < TM; i++) ra[i] = As[k][tr * TM + i];
            #pragma unroll
            for (int j = 0; j < TN; j++) rb[j] = Bs[k][tc * TN + j];
            #pragma unroll
            for (int i = 0; i < TM; i++)
                #pragma unroll
                for (int j = 0; j < TN; j++)
                    acc[i][j] += ra[i] * rb[j];
        }
        __syncthreads();
    }
    #pragma unroll
    for (int i = 0; i < TM; i++) {
        int gr = blockRow + tr * TM + i;
        if (gr >= M) continue;
        #pragma unroll
        for (int j = 0; j < TN; j += 4) {
            float4 v = make_float4(acc[i][j], acc[i][j+1], acc[i][j+2], acc[i][j+3]);
            *reinterpret_cast<float4*>(C + (size_t)gr * 128 + tc * TN + j) = v;
        }
    }
}

// ---------------- CSR gather conv (C=128), fused bias + activation -----------
// act 0: leaky_relu(t); act 1: leaky_relu(t)+t
__global__ void k_gather(const float* __restrict__ bias, int act) {
    int warp = (blockIdx.x * blockDim.x + threadIdx.x) >> 5;
    int lane = threadIdx.x & 31;
    if (warp >= NN) return;
    int v = warp;
    float dv = g_dinv[v];
    float selfw = dv * dv;

    float4 h = reinterpret_cast<const float4*>(g_H + (size_t)v * 128)[lane];
    float4 acc = make_float4(selfw * h.x, selfw * h.y, selfw * h.z, selfw * h.w);

    int s = g_rowStart[v], e = g_rowStart[v + 1];
    int i = s;
    for (; i + 1 < e; i += 2) {
        int s0 = g_srcSorted[i];     float w0 = g_wSorted[i];
        int s1 = g_srcSorted[i + 1]; float w1 = g_wSorted[i + 1];
        float4 h0 = reinterpret_cast<const float4*>(g_H + (size_t)s0 * 128)[lane];
        float4 h1 = reinterpret_cast<const float4*>(g_H + (size_t)s1 * 128)[lane];
        acc.x += w0 * h0.x + w1 * h1.x;
        acc.y += w0 * h0.y + w1 * h1.y;
        acc.z += w0 * h0.z + w1 * h1.z;
        acc.w += w0 * h0.w + w1 * h1.w;
    }
    if (i < e) {
        int s0 = g_srcSorted[i]; float w0 = g_wSorted[i];
        float4 h0 = reinterpret_cast<const float4*>(g_H + (size_t)s0 * 128)[lane];
        acc.x += w0 * h0.x; acc.y += w0 * h0.y; acc.z += w0 * h0.z; acc.w += w0 * h0.w;
    }
    float4 b = reinterpret_cast<const float4*>(bias)[lane];
    float t[4] = { acc.x + b.x, acc.y + b.y, acc.z + b.z, acc.w + b.w };
    float4 o;
    if (act == 0) {
        o = make_float4(lrelu(t[0]), lrelu(t[1]), lrelu(t[2]), lrelu(t[3]));
    } else {  // lrelu(t)+t : 2t if t>=0 else 1.01t
        o.x = t[0] >= 0.f ? 2.f * t[0] : 1.01f * t[0];
        o.y = t[1] >= 0.f ? 2.f * t[1] : 1.01f * t[1];
        o.z = t[2] >= 0.f ? 2.f * t[2] : 1.01f * t[2];
        o.w = t[3] >= 0.f ? 2.f * t[3] : 1.01f * t[3];
    }
    reinterpret_cast<float4*>(g_X + (size_t)v * 128)[lane] = o;
}

// ---------------- output conv: GEMV + 1-channel gather -----------------------
__global__ void k_gemv1(const float* __restrict__ Wout) {
    int warp = (blockIdx.x * blockDim.x + threadIdx.x) >> 5;
    int lane = threadIdx.x & 31;
    if (warp >= NN) return;
    float4 x = reinterpret_cast<const float4*>(g_X + (size_t)warp * 128)[lane];
    float4 w = reinterpret_cast<const float4*>(Wout)[lane];
    float p = x.x * w.x + x.y * w.y + x.z * w.z + x.w * w.w;
    #pragma unroll
    for (int off = 16; off; off >>= 1) p += __shfl_xor_sync(0xffffffffu, p, off);
    if (lane == 0) g_h1[warp] = p;
}

__global__ void k_gather1(const float* __restrict__ b_out) {
    int warp = (blockIdx.x * blockDim.x + threadIdx.x) >> 5;
    int lane = threadIdx.x & 31;
    if (warp >= NN) return;
    int v = warp;
    int s = g_rowStart[v], e = g_rowStart[v + 1];
    float local = 0.f;
    for (int i = s + lane; i < e; i += 32)
        local += g_wSorted[i] * g_h1[g_srcSorted[i]];
    #pragma unroll
    for (int off = 16; off; off >>= 1) local += __shfl_xor_sync(0xffffffffu, local, off);
    if (lane == 0) {
        float dv = g_dinv[v];
        float t = b_out[0] + dv * dv * g_h1[v] + local;
        g_xvec[v] = lrelu(t);
    }
}

// ---------------- fc1: h[128] = relu(xvec @ W_fc1 + b_fc1) -------------------
__global__ void k_fc1(const float* __restrict__ W) {
    int tid = threadIdx.x;                        // 128 threads
    int rows = (NN + gridDim.x - 1) / gridDim.x;
    int r0 = blockIdx.x * rows;
    int r1 = min(r0 + rows, NN);
    float acc = 0.f;
    for (int r = r0; r < r1; r++)
        acc += g_xvec[r] * W[(size_t)r * 128 + tid];
    atomicAdd(&g_fc1acc[tid], acc);
}

// ---------------- fc2: out[PP] = relu(relu(h) @ W_fc2 + b_fc2) ---------------
__global__ void k_fc2(const float* __restrict__ b1,
                      const float* __restrict__ W2,
                      const float* __restrict__ b2,
                      float* __restrict__ out) {
    __shared__ float h[128];
    int tid = threadIdx.x;
    if (tid < 128) {
        float t = g_fc1acc[tid] + b1[tid];
        h[tid] = t > 0.f ? t : 0.f;
    }
    __syncthreads();
    int j = blockIdx.x * blockDim.x + tid;
    if (j >= PP) return;
    float acc = b2[j];
    #pragma unroll
    for (int k = 0; k < 128; k++)
        acc += h[k] * W2[(size_t)k * PP + j];
    out[j] = acc > 0.f ? acc : 0.f;
}

// ---------------- launch -----------------------------------------------------
extern "C" void kernel_launch(void* const* d_in, const int* in_sizes, int n_in,
                              void* d_out, int out_size) {
    const float*         feature = (const float*)d_in[0];
    const unsigned char* mask    = (const unsigned char*)d_in[1];
    const int*           edge    = (const int*)d_in[2];
    const float*         emb     = (const float*)d_in[3];
    const float*         W_in    = (const float*)d_in[4];
    const float*         b_in    = (const float*)d_in[5];
    const float*         W_gcn   = (const float*)d_in[6];
    const float*         b_gcn   = (const float*)d_in[7];
    const float*         W_out   = (const float*)d_in[8];
    const float*         b_out   = (const float*)d_in[9];
    const float*         W_fc1   = (const float*)d_in[10];
    const float*         b_fc1   = (const float*)d_in[11];
    const float*         W_fc2   = (const float*)d_in[12];
    const float*         b_fc2   = (const float*)d_in[13];
    float*               out     = (float*)d_out;

    const int* esrc = edge;
    const int* edst = edge + EE;

    const int nodeBlocks  = (NN + 255) / 256;
    const int edgeBlocks  = (EE + 255) / 256;
    const int copyBlocks  = (int)(((size_t)NN * FF / 4 + 255) / 256);
    const int warpBlocks  = (int)(((size_t)NN * 32 + 255) / 256);
    const int gemmBlocks  = (NN + 127) / 128;

    // setup
    k_poi      <<<nodeBlocks, 256>>>(mask, feature);
    k_build_ef <<<copyBlocks, 256>>>(feature);
    k_fix_ef   <<<nodeBlocks, 256>>>(emb);
    k_deg_init <<<nodeBlocks, 256>>>();
    k_deg_count<<<edgeBlocks, 256>>>(edst);
    k_scan     <<<1, 1024>>>();
    k_bucket   <<<edgeBlocks, 256>>>(esrc, edst);
    k_zero128  <<<1, 128>>>();

    // input conv: H = EF @ W_in ; X = lrelu(scatter + b_in)
    k_sgemm<FF, true><<<gemmBlocks, 256>>>(W_in);
    k_gather<<<warpBlocks, 256>>>(b_in, /*act=*/0);

    // 4 hidden GcnUnits: t = conv(X); X = lrelu(t)+t
    for (int l = 0; l < LL; l++) {
        k_sgemm<CC, false><<<gemmBlocks, 256>>>(W_gcn + (size_t)l * CC * CC);
        k_gather<<<warpBlocks, 256>>>(b_gcn + (size_t)l * CC, /*act=*/1);
    }

    // output conv (C=1) + lrelu
    k_gemv1  <<<warpBlocks, 256>>>(W_out);
    k_gather1<<<warpBlocks, 256>>>(b_out);

    // fc head
    k_fc1<<<256, 128>>>(W_fc1);
    k_fc2<<<(PP + 255) / 256, 256>>>(b_fc1, W_fc2, b_fc2, out);
}